// round 17
// baseline (speedup 1.0000x reference)
#include <cuda_runtime.h>

#define BB 8
#define CC 4
#define HH 512
#define WW 512
#define RPW 16                         // rows per warp strip
#define NSTRIPS (HH / RPW)             // 32
#define NPLANE (BB * CC)               // 32
#define NTASK (NPLANE * NSTRIPS * 2)   // 2048 warp-tasks (2 col groups of 256)
#define NT 224
#define WPB 7                          // warps per block
#define NBLK ((NTASK + WPB - 1) / WPB) // 293

#define NEG4F 0xC0800000u              // -4.0f bits (u-domain padded s)

__device__ float4 g_part[NTASK];
__device__ int g_ctr = 0;

// u = tanh(x/2); p = sigmoid(x) = 0.5u + 0.5. All Sobel math in u-domain.
__device__ __forceinline__ float uhalf(float x) {
    float t;
    asm("tanh.approx.f32 %0, %1;" : "=f"(t) : "f"(0.5f * x));
    return t;
}
__device__ __forceinline__ unsigned prmt(unsigned a, unsigned b, unsigned s) {
    unsigned r;
    asm("prmt.b32 %0, %1, %2, %3;" : "=r"(r) : "r"(a), "r"(b), "r"(s));
    return r;
}
__device__ __forceinline__ float fsel(float v, float w, unsigned m) {
    return __uint_as_float((__float_as_uint(v) & m) | (__float_as_uint(w) & ~m));
}
__device__ __forceinline__ float fand(float v, unsigned m) {
    return __uint_as_float(__float_as_uint(v) & m);
}

struct Row {
    float s[8], d[8];             // horizontal sobel partials (u-domain)
    unsigned sb0, sb1, db0, db1;  // packed-byte partials (targets)
};

// Unguarded, BRANCH-FREE fetch: row gr MUST be in [0, HH).
// offE: per-lane edge-load offset; interior lanes broadcast-load the row base.
template <bool DICE>
__device__ __forceinline__ Row fetch(const float* __restrict__ lg,
                                     const float* __restrict__ tg,
                                     int gr, int c0, int lane, int offE,
                                     bool lE, bool rE,
                                     float& s_ut, float& s_u, int& s_ti)
{
    const float* rowp = lg + (size_t)gr * WW + c0;
    const float* rowt = tg + (size_t)gr * WW + c0;
    float4 xa = __ldg((const float4*)rowp);
    float4 xb = __ldg((const float4*)(rowp + 4));
    float4 ta = __ldg((const float4*)rowt);
    float4 tb = __ldg((const float4*)(rowt + 4));
    // unconditional edge loads (interior lanes hit the broadcast row base)
    float xe = __ldg(rowp + offE);
    float te = __ldg(rowt + offE);

    float u[8];
    u[0] = uhalf(xa.x); u[1] = uhalf(xa.y); u[2] = uhalf(xa.z); u[3] = uhalf(xa.w);
    u[4] = uhalf(xb.x); u[5] = uhalf(xb.y); u[6] = uhalf(xb.z); u[7] = uhalf(xb.w);
    unsigned q1 = prmt(__float_as_uint(ta.x), __float_as_uint(ta.y), 0x0073u);
    unsigned q2 = prmt(__float_as_uint(ta.z), __float_as_uint(ta.w), 0x7300u);
    unsigned tw0 = (q1 | q2) & 0x01010101u;
    unsigned q3 = prmt(__float_as_uint(tb.x), __float_as_uint(tb.y), 0x0073u);
    unsigned q4 = prmt(__float_as_uint(tb.z), __float_as_uint(tb.w), 0x7300u);
    unsigned tw1 = (q3 | q4) & 0x01010101u;

    if (DICE) {
        s_ut = __fmaf_rn(u[0], ta.x, s_ut);
        s_ut = __fmaf_rn(u[1], ta.y, s_ut);
        s_ut = __fmaf_rn(u[2], ta.z, s_ut);
        s_ut = __fmaf_rn(u[3], ta.w, s_ut);
        s_ut = __fmaf_rn(u[4], tb.x, s_ut);
        s_ut = __fmaf_rn(u[5], tb.y, s_ut);
        s_ut = __fmaf_rn(u[6], tb.z, s_ut);
        s_ut = __fmaf_rn(u[7], tb.w, s_ut);
        s_u += ((u[0] + u[1]) + (u[2] + u[3])) + ((u[4] + u[5]) + (u[6] + u[7]));
        s_ti += __popc(tw0) + __popc(tw1);
    }

    // packed neighbor exchange: u value (LSB zeroed) | target bit
    unsigned pk7 = (__float_as_uint(u[7]) & ~1u) | (tw1 >> 24);
    unsigned pk0 = (__float_as_uint(u[0]) & ~1u) | (tw0 & 1u);
    unsigned rl = __shfl_up_sync(0xffffffffu, pk7, 1);
    unsigned rr = __shfl_down_sync(0xffffffffu, pk0, 1);
    float ul = __uint_as_float(rl & ~1u);
    float ur = __uint_as_float(rr & ~1u);
    unsigned tli = rl & 1u, tri = rr & 1u;

    // edge-lane fixups: warp-uniform SELs, no divergence
    float ue = uhalf(xe);
    unsigned teb = __float_as_uint(te) >> 29;
    if (lane == 0)  { ul = lE ? ue : -1.f; tli = lE ? teb : 0u; }
    if (lane == 31) { ur = rE ? ue : -1.f; tri = rE ? teb : 0u; }

    Row h;
    h.s[0] = __fmaf_rn(2.f, u[0], ul + u[1]); h.d[0] = u[1] - ul;
    #pragma unroll
    for (int i = 1; i < 7; i++) {
        h.s[i] = __fmaf_rn(2.f, u[i], u[i-1] + u[i+1]);
        h.d[i] = u[i+1] - u[i-1];
    }
    h.s[7] = __fmaf_rn(2.f, u[7], u[6] + ur); h.d[7] = ur - u[6];

    unsigned wl0 = (tw0 << 8) | tli;
    unsigned wr0 = (tw0 >> 8) | ((tw1 & 0xffu) << 24);
    h.sb0 = wl0 + 2u * tw0 + wr0;
    h.db0 = (wr0 + 0x02020202u) - wl0;
    unsigned wl1 = (tw1 << 8) | (tw0 >> 24);
    unsigned wr1 = (tw1 >> 8) | (tri << 24);
    h.sb1 = wl1 + 2u * tw1 + wr1;
    h.db1 = (wr1 + 0x02020202u) - wl1;
    return h;
}

// Halo fetch: row may be out of range. Padded probs row: u=-1 => s=-4, d=0.
// Padded target row: sb=0, db biased zero.
__device__ __forceinline__ Row fetch_halo(const float* __restrict__ lg,
                                          const float* __restrict__ tg,
                                          int gr, int c0, int lane, int offE,
                                          bool lE, bool rE)
{
    const unsigned msk = ((unsigned)gr < (unsigned)HH) ? 0xffffffffu : 0u;
    const float spad = __uint_as_float(NEG4F);
    int grc = gr < 0 ? 0 : (gr >= HH ? HH - 1 : gr);
    float dut = 0.f, du = 0.f; int dti = 0;
    Row h = fetch<false>(lg, tg, grc, c0, lane, offE, lE, rE, dut, du, dti);
    #pragma unroll
    for (int i = 0; i < 8; i++) {
        h.s[i] = fsel(h.s[i], spad, msk);
        h.d[i] = fand(h.d[i], msk);
    }
    h.sb0 &= msk; h.sb1 &= msk;
    h.db0 = (h.db0 & msk) | (0x02020202u & ~msk);
    h.db1 = (h.db1 & msk) | (0x02020202u & ~msk);
    return h;
}

__device__ __forceinline__ int combine(const Row& h0, const Row& h1, const Row& h2)
{
    bool pb[8];
    #pragma unroll
    for (int i = 0; i < 8; i++) {
        float gx = __fmaf_rn(2.f, h1.d[i], h0.d[i] + h2.d[i]);
        float gy = h2.s[i] - h0.s[i];
        // u-domain: true mag^2 = 0.25*(gx^2+gy^2); (mag > 0.5) <=> (... > 1)
        pb[i] = __fmaf_rn(gx, gx, gy * gy) > 1.0f;
    }
    unsigned hx0 = h0.db0 + 2u * h1.db0 + h2.db0;
    unsigned hy0 = (h2.sb0 + 0x04040404u) - h0.sb0;
    unsigned cmb0 = (hx0 ^ 0x08080808u) | (hy0 ^ 0x04040404u);
    unsigned hx1 = h0.db1 + 2u * h1.db1 + h2.db1;
    unsigned hy1 = (h2.sb1 + 0x04040404u) - h0.sb1;
    unsigned cmb1 = (hx1 ^ 0x08080808u) | (hy1 ^ 0x04040404u);

    int m = 0;
    m += (int)(pb[0] != ((cmb0 & 0x000000FFu) != 0));
    m += (int)(pb[1] != ((cmb0 & 0x0000FF00u) != 0));
    m += (int)(pb[2] != ((cmb0 & 0x00FF0000u) != 0));
    m += (int)(pb[3] != ((cmb0 >> 24) != 0));
    m += (int)(pb[4] != ((cmb1 & 0x000000FFu) != 0));
    m += (int)(pb[5] != ((cmb1 & 0x0000FF00u) != 0));
    m += (int)(pb[6] != ((cmb1 & 0x00FF0000u) != 0));
    m += (int)(pb[7] != ((cmb1 >> 24) != 0));
    return m;
}

__global__ __launch_bounds__(NT, 2) void loss_fused(
    const float* __restrict__ logits, const float* __restrict__ targets,
    const float* __restrict__ cw, float* __restrict__ out)
{
    __shared__ float s_dice[NPLANE];
    __shared__ float s_mm[NPLANE];
    __shared__ int s_isLast;

    const int tid = threadIdx.x;
    const int lane = tid & 31;
    const int w = tid >> 5;
    const int gw = blockIdx.x * WPB + w;         // warp-task id

    if (gw < NTASK) {
        const int cg    = gw & 1;                    // column group 0..1
        const int strip = (gw >> 1) & (NSTRIPS - 1); // 0..31
        const int plane = gw >> 6;                   // 0..31
        const int c0 = cg * 256 + lane * 8;
        const bool lE = (cg > 0);
        const bool rE = (cg < 1);
        const int row0 = strip * RPW;

        // per-lane edge-load offset; interior lanes broadcast the row base
        int offE = -8 * lane;
        if (lane == 0)  offE = lE ? -1 : 0;
        if (lane == 31) offE = rE ? 8 : -8 * 31;

        const float* lg = logits  + (size_t)plane * HH * WW;
        const float* tg = targets + (size_t)plane * HH * WW;

        float s_ut = 0.f, s_u = 0.f;
        int s_ti = 0, s_mi = 0;

        // prologue: top halo (masked) + first interior row
        Row h0 = fetch_halo(lg, tg, row0 - 1, c0, lane, offE, lE, rE);
        Row h1 = fetch<true>(lg, tg, row0, c0, lane, offE, lE, rE, s_ut, s_u, s_ti);

        // hot loop: rows row0+1 .. row0+RPW-1 always in range — branch-free
        #pragma unroll
        for (int k = 0; k < RPW - 1; k++) {
            Row h2 = fetch<true>(lg, tg, row0 + k + 1, c0, lane, offE, lE, rE,
                                 s_ut, s_u, s_ti);
            s_mi += combine(h0, h1, h2);
            h0 = h1; h1 = h2;
        }
        // epilogue: bottom halo (masked)
        {
            Row h2 = fetch_halo(lg, tg, row0 + RPW, c0, lane, offE, lE, rE);
            s_mi += combine(h0, h1, h2);
        }

        // u-domain -> p-domain corrections (128 dice px per thread)
        float s_t = (float)s_ti;
        float s_pt = 0.5f * (s_ut + s_t);            // sum p*t
        float s_p  = __fmaf_rn(0.5f, s_u, 64.0f);    // sum p = 0.5*sum u + 64
        float s_m  = (float)s_mi;

        // ---- warp reduce; lane0 writes the task partial directly ----
        #pragma unroll
        for (int o = 16; o > 0; o >>= 1) {
            s_pt += __shfl_down_sync(0xffffffffu, s_pt, o);
            s_p  += __shfl_down_sync(0xffffffffu, s_p,  o);
            s_t  += __shfl_down_sync(0xffffffffu, s_t,  o);
            s_m  += __shfl_down_sync(0xffffffffu, s_m,  o);
        }
        if (lane == 0) {
            g_part[gw] = make_float4(s_pt, s_p, s_t, s_m);
            __threadfence();
        }
    }
    __syncthreads();
    if (tid == 0) {
        int v = atomicAdd(&g_ctr, 1);
        s_isLast = (v == NBLK - 1);
    }
    __syncthreads();

    // ---- final reduction in last block ----
    if (s_isLast) {
        __threadfence();
        if (tid < NPLANE) {
            float a = 0.f, b = 0.f, c2 = 0.f, m = 0.f;
            #pragma unroll 4
            for (int s = 0; s < NTASK / NPLANE; s++) {
                float4 v = g_part[tid * (NTASK / NPLANE) + s];
                a += v.x; b += v.y; c2 += v.z; m += v.w;
            }
            s_dice[tid] = (2.0f * a + 1.0f) / (b + c2 + 1.0f);  // SMOOTH=1
            s_mm[tid] = m;
        }
        __syncthreads();
        if (tid == 0) {
            float mt = 0.0f;
            #pragma unroll
            for (int j = 0; j < NPLANE; j++) mt += s_mm[j];

            float wsum = 0.0f, dl = 0.0f;
            #pragma unroll
            for (int c = 0; c < CC; c++) {
                float acc = 0.0f;
                #pragma unroll
                for (int b = 0; b < BB; b++) acc += s_dice[b * CC + c];
                dl += cw[c] * (1.0f - acc / (float)BB);
                wsum += cw[c];
            }
            dl /= wsum;
            float bl = 100.0f * mt / (float)((long long)BB * CC * HH * WW);
            out[0] = 0.7f * dl + 0.3f * bl;
            g_ctr = 0;   // reset for next graph replay
        }
    }
}

extern "C" void kernel_launch(void* const* d_in, const int* in_sizes, int n_in,
                              void* d_out, int out_size)
{
    const float* logits  = (const float*)d_in[0];
    const float* targets = (const float*)d_in[1];
    const float* cw      = (const float*)d_in[2];

    loss_fused<<<NBLK, NT>>>(logits, targets, cw, (float*)d_out);
}